// round 10
// baseline (speedup 1.0000x reference)
#include <cuda_runtime.h>
#include <math.h>

// Problem constants
#define N_POINTS 4096
#define N_VIEWS  4
#define IMG_H    128
#define IMG_W    128
#define N_PIX    (N_VIEWS * IMG_H * IMG_W)   // 65536
#define TOPK     5
#define R2F      0.0004f     // 0.02^2
#define CAP      40          // per-pixel hit capacity (max observed ~20)
#define BATCH    8           // prefetch width in raster (MLP)

// cos(15deg), sin(15deg)
#define CE 0.96592582628906831f
#define SE 0.25881904510252074f

// Camera axes per view (columns of R): X_view = pcd . axis + T, T = (0,0,1.5)
__constant__ float c_ax[N_VIEWS][3] = {
    {-1.f, 0.f, 0.f}, {0.f, 0.f, 1.f}, {1.f, 0.f, 0.f}, {0.f, 0.f, -1.f}};
__constant__ float c_ay[N_VIEWS][3] = {
    {0.f, CE, -SE}, {-SE, CE, 0.f}, {0.f, CE, SE}, {SE, CE, 0.f}};
__constant__ float c_az[N_VIEWS][3] = {
    {0.f, -SE, -CE}, {-CE, -SE, 0.f}, {0.f, -SE, CE}, {CE, -SE, 0.f}};

// Plane-major per-pixel hit lists: hit j of pixel p at g_hits[j][p].
// (z, alpha, color, pad). Coalesced per-plane reads in raster.
__device__ float4 g_hits[CAP][N_PIX];
__device__ int    g_hcnt[N_PIX];      // zero-init at load; raster resets after read

// One thread per (point, view). 4 consecutive threads share a point.
__global__ void prep_kernel(const float* __restrict__ pcd,
                            const float* __restrict__ displace,
                            const float* __restrict__ init_colors,
                            float* __restrict__ out_colors) {
    int t = blockIdx.x * blockDim.x + threadIdx.x;
    if (t >= N_POINTS * N_VIEWS) return;
    int n = t >> 2;
    int v = t & 3;

    float x = pcd[3 * n + 0];
    float y = pcd[3 * n + 1];
    float z = pcd[3 * n + 2];
    float col = 1.0f / (1.0f + expf(-(init_colors[n] + displace[n])));
    if (v == 0) out_colors[n] = col;

    float px = x * c_ax[v][0] + y * c_ax[v][1] + z * c_ax[v][2];
    float py = x * c_ay[v][0] + y * c_ay[v][1] + z * c_ay[v][2];
    float zv = x * c_az[v][0] + y * c_az[v][1] + z * c_az[v][2] + 1.5f;
    float pz = (zv - 0.01f) / 99.99f;
    if (pz <= 0.0f) return;

    // pixel-center bbox: xf(xi) = 1 - (2xi+1)/128; disk spans <= 3 centers/axis
    const float rexp = 0.0201f;
    int ilo = max(0,   (int)ceilf ((1.0f - px - rexp) * 64.0f - 0.5f));
    int ihi = min(127, (int)floorf((1.0f - px + rexp) * 64.0f - 0.5f));
    int jlo = max(0,   (int)ceilf ((1.0f - py - rexp) * 64.0f - 0.5f));
    int jhi = min(127, (int)floorf((1.0f - py + rexp) * 64.0f - 0.5f));

    const float inv128 = 0.0078125f;

    // Fully unrolled 3x3 predicated scatter: 9 independent tests,
    // independent atomics issued back-to-back (latency overlapped).
    int   pp[9];
    float aa[9];
    bool  ok[9];
#pragma unroll
    for (int dj = 0; dj < 3; dj++) {
        int yi = jlo + dj;
        float yf = 1.0f - (float)(2 * yi + 1) * inv128;
        float dy = py - yf;
        float dy2 = dy * dy;
#pragma unroll
        for (int di = 0; di < 3; di++) {
            int e = dj * 3 + di;
            int xi = ilo + di;
            float xf = 1.0f - (float)(2 * xi + 1) * inv128;
            float dx = px - xf;
            float d2 = fmaf(dx, dx, dy2);
            ok[e] = (yi <= jhi) && (xi <= ihi) && (d2 < R2F);
            pp[e] = ((v * IMG_H) + yi) * IMG_W + xi;
            aa[e] = 1.0f - d2 / R2F;
        }
    }
    int ss[9];
#pragma unroll
    for (int e = 0; e < 9; e++)
        ss[e] = ok[e] ? atomicAdd(&g_hcnt[pp[e]], 1) : CAP;
#pragma unroll
    for (int e = 0; e < 9; e++)
        if (ss[e] < CAP)
            g_hits[ss[e]][pp[e]] = make_float4(pz, aa[e], col, 0.0f);
}

// One thread per pixel: gather own hits (plane-major, coalesced, batched MLP),
// top-5 by z, over-composite.
__global__ void __launch_bounds__(128) raster_kernel(float* __restrict__ out) {
    int p = blockIdx.x * 128 + threadIdx.x;

    // count and plane-0 hit load concurrently (independent addresses)
    int n = g_hcnt[p];
    float4 h0 = g_hits[0][p];
    g_hcnt[p] = 0;                 // reset for next graph replay (same thread: ordered)
    if (n > CAP) n = CAP;

    const float INF = __int_as_float(0x7f800000);
    float zk[TOPK], ak[TOPK], ck[TOPK];
#pragma unroll
    for (int k = 0; k < TOPK; k++) { zk[k] = INF; ak[k] = 0.0f; ck[k] = 0.0f; }

    if (n > 0) { zk[0] = h0.x; ak[0] = h0.y; ck[0] = h0.z; }

    // remaining hits: chunks of BATCH independent loads, then insert from regs
    for (int base = 1; base < n; base += BATCH) {
        float4 h[BATCH];
        int cnt = n - base;
        if (cnt > BATCH) cnt = BATCH;
#pragma unroll
        for (int i = 0; i < BATCH; i++)
            if (i < cnt) h[i] = g_hits[base + i][p];
#pragma unroll
        for (int i = 0; i < BATCH; i++) {
            if (i < cnt) {
                float nz = h[i].x, na = h[i].y, nc = h[i].z;
#pragma unroll
                for (int k = 0; k < TOPK; k++) {
                    if (nz < zk[k]) {
                        float t;
                        t = zk[k]; zk[k] = nz; nz = t;
                        t = ak[k]; ak[k] = na; na = t;
                        t = ck[k]; ck[k] = nc; nc = t;
                    }
                }
            }
        }
    }

    // front-to-back over-composite (empty slots contribute 0)
    float trans = 1.0f, pixv = 0.0f;
#pragma unroll
    for (int k = 0; k < TOPK; k++) {
        pixv += ak[k] * trans * ck[k];
        trans *= (1.0f - ak[k]);
    }

    int base = p * 3;
    out[base + 0] = pixv;
    out[base + 1] = pixv;
    out[base + 2] = pixv;
}

extern "C" void kernel_launch(void* const* d_in, const int* in_sizes, int n_in,
                              void* d_out, int out_size) {
    const float* pcd         = (const float*)d_in[0];
    const float* displace    = (const float*)d_in[1];
    const float* init_colors = (const float*)d_in[2];
    float* out = (float*)d_out;

    // colors_ tail lives after the 4*128*128*3 image block
    float* out_colors = out + (size_t)N_PIX * 3;

    prep_kernel<<<(N_POINTS * N_VIEWS + 127) / 128, 128>>>(pcd, displace, init_colors, out_colors);
    raster_kernel<<<N_PIX / 128, 128>>>(out);
}